// round 6
// baseline (speedup 1.0000x reference)
#include <cuda_runtime.h>

#define N     4096
#define IT    30
#define G     128            // persistent blocks, 1/SM, co-resident
#define TPB   1024           // 32 warps
#define TOTF4 ((size_t)N * N / 4)

// Scratch (__device__ globals: allocation-free rule)
static __device__ float g_B0[(size_t)N * N];   // (mean+std*eps)*log2(e)/TAU
static __device__ float g_r[N];
static __device__ float g_c[N];
static __device__ float g_part[(size_t)G * N]; // [block][col] partial col sums
static __device__ unsigned g_arrive;           // barrier counter (0-init)
static __device__ unsigned g_gen;              // barrier generation (monotonic)

__device__ __forceinline__ float ex2(float x) {
    float y; asm("ex2.approx.ftz.f32 %0, %1;" : "=f"(y) : "f"(x)); return y;
}
__device__ __forceinline__ float lg2(float x) {
    float y; asm("lg2.approx.f32 %0, %1;" : "=f"(y) : "f"(x)); return y;
}

// Grid-wide barrier (all G blocks co-resident by construction).
__device__ __forceinline__ void grid_bar() {
    __syncthreads();
    if (threadIdx.x == 0) {
        __threadfence();
        unsigned gen = *((volatile unsigned*)&g_gen);
        if (atomicAdd(&g_arrive, 1u) == (unsigned)G - 1u) {
            g_arrive = 0u;
            __threadfence();
            *((volatile unsigned*)&g_gen) = gen + 1u;
        } else {
            while (*((volatile unsigned*)&g_gen) == gen) { }
        }
        __threadfence();
    }
    __syncthreads();
}

__global__ void __launch_bounds__(TPB, 1)
sinkhorn_persistent(const float* __restrict__ eps,
                    const float* __restrict__ mean,
                    const float* __restrict__ stdv,
                    float* __restrict__ out) {
    const int b    = blockIdx.x;
    const int t    = threadIdx.x;
    const int lane = t & 31;
    const int warp = t >> 5;               // 0..31
    const unsigned gtid = b * TPB + t;

    __shared__ float sC[N];                // staged c (16 KB)
    __shared__ float sRow[8][4];           // 4-warp row partials
    __shared__ float sR[8];                // r_new of current sub-stripe
    __shared__ float sPart[32][33];        // combine scratch (padded)

    // ---------------- Phase 0: setup -------------------------------------
    {
        const float SCALE = 0.72134752044448170368f;  // log2(e)/TAU, TAU=2
        const float4* e4 = (const float4*)eps;
        const float4* m4 = (const float4*)mean;
        const float4* s4 = (const float4*)stdv;
        float4* b4 = (float4*)g_B0;
        for (size_t i = gtid; i < TOTF4; i += (size_t)G * TPB) {
            float4 e = e4[i], m = m4[i], s = s4[i];
            float4 o;
            o.x = (m.x + s.x * e.x) * SCALE;
            o.y = (m.y + s.y * e.y) * SCALE;
            o.z = (m.z + s.z * e.z) * SCALE;
            o.w = (m.w + s.w * e.w) * SCALE;
            b4[i] = o;
        }
        float4 z = make_float4(0.f, 0.f, 0.f, 0.f);
        if (gtid < 1024)      ((float4*)g_c)[gtid] = z;
        else if (gtid < 2048) ((float4*)g_r)[gtid - 1024] = z;
    }
    grid_bar();

    const int i0 = b * 32;                 // this block's exclusive row stripe
    const int rloc = warp >> 2;            // row within sub-stripe (0..7)
    const int q    = warp & 3;             // quarter-row (0..3)

    for (int it = 0; it < IT; it++) {
        // stage c into shared (cross-block mutable -> ldcg)
        ((float4*)sC)[t] = __ldcg(((const float4*)g_c) + t);
        __syncthreads();
        const float4 cA = ((const float4*)sC)[t];

        float4 acc = make_float4(0.f, 0.f, 0.f, 0.f);

        // ------ 4 sub-stripes of 8 rows: row pass then L1-hot col pass ----
        #pragma unroll 1
        for (int sub = 0; sub < 4; sub++) {
            const int r0 = i0 + sub * 8;

            // row phase: 4 warps per row, disjoint quarter-rows
            {
                const int row = r0 + rloc;
                const float rp = g_r[row];          // block-exclusive -> L1 ok
                const float4* __restrict__ rowp =
                    (const float4*)(g_B0 + (size_t)row * N);
                float s = 0.f;
                #pragma unroll
                for (int k = 0; k < 8; k++) {
                    const int slot = q * 256 + lane + 32 * k;
                    float4 bb = rowp[slot];
                    float4 cc = ((const float4*)sC)[slot];
                    s += ex2((bb.x - cc.x) - rp);
                    s += ex2((bb.y - cc.y) - rp);
                    s += ex2((bb.z - cc.z) - rp);
                    s += ex2((bb.w - cc.w) - rp);
                }
                #pragma unroll
                for (int o = 16; o > 0; o >>= 1)
                    s += __shfl_xor_sync(0xffffffffu, s, o);
                if (lane == 0) sRow[rloc][q] = s;
            }
            __syncthreads();
            if (t < 8) {
                float S = (sRow[t][0] + sRow[t][1]) + (sRow[t][2] + sRow[t][3]);
                float rn = g_r[r0 + t] + lg2(S);
                sR[t] = rn;
                g_r[r0 + t] = rn;
            }
            __syncthreads();

            // col phase: thread owns float4 slot t; sub-stripe is L1-hot
            #pragma unroll
            for (int i = 0; i < 8; i++) {
                const float rv = sR[i];
                float4 bb = ((const float4*)(g_B0 + (size_t)(r0 + i) * N))[t];
                acc.x += ex2((bb.x - cA.x) - rv);
                acc.y += ex2((bb.y - cA.y) - rv);
                acc.z += ex2((bb.z - cA.z) - rv);
                acc.w += ex2((bb.w - cA.w) - rv);
            }
            __syncthreads();               // protect sRow/sR for next sub
        }

        // write column partials (coalesced [block][col])
        ((float4*)(g_part + (size_t)b * N))[t] = acc;
        grid_bar();                        // all partials visible

        // combine: block b folds its own 32 columns
        {
            const int col = b * 32 + lane;
            float s4 = 0.f;
            #pragma unroll
            for (int p = 0; p < 4; p++)
                s4 += __ldcg(g_part + (size_t)(warp * 4 + p) * N + col);
            sPart[warp][lane] = s4;
            __syncthreads();
            if (t < 32) {
                float s = 0.f;
                #pragma unroll
                for (int k = 0; k < 32; k++) s += sPart[k][t];
                const int j = b * 32 + t;
                g_c[j] = __ldcg(g_c + j) + lg2(s);
            }
        }
        grid_bar();                        // c visible to all
    }

    // ---------------- Final: out = 2^(B0 - r(i) - c(j)) ------------------
    {
        const float4* b4 = (const float4*)g_B0;
        float4* o4 = (float4*)out;
        for (size_t i = gtid; i < TOTF4; i += (size_t)G * TPB) {
            int row = (int)(i >> 10);
            int cf  = (int)(i & 1023);
            float rv  = __ldcg(g_r + row);
            float4 cv = __ldcg(((const float4*)g_c) + cf);
            float4 bb = b4[i];
            float4 o;
            o.x = ex2((bb.x - cv.x) - rv);
            o.y = ex2((bb.y - cv.y) - rv);
            o.z = ex2((bb.z - cv.z) - rv);
            o.w = ex2((bb.w - cv.w) - rv);
            o4[i] = o;
        }
    }
}

extern "C" void kernel_launch(void* const* d_in, const int* in_sizes, int n_in,
                              void* d_out, int out_size) {
    const float* eps  = (const float*)d_in[0];
    const float* mean = (const float*)d_in[1];
    const float* stdv = (const float*)d_in[2];
    sinkhorn_persistent<<<G, TPB>>>(eps, mean, stdv, (float*)d_out);
}